// round 5
// baseline (speedup 1.0000x reference)
#include <cuda_runtime.h>
#include <stdint.h>

// TwoHotEmbedding: out[t,:] = w[i1[t],:]              if i1[t]==i2[t]
//                             w[i1[t],:] + w[i2[t],:]  otherwise
// B*S = 65536 tokens, D = 256 floats per row (1024 B = 32 lanes x 32 B).
//
// Model (R1-R4 evidence): kernel is pinned at ~24.3us by the chip-wide LTS
// (L2 fabric) cap -- 201 MB of L2-crossing traffic (134 MB gather reads +
// 67 MB streaming writes) at ~8.3 TB/s, invariant under DRAM-byte and
// occupancy changes. Traffic is algorithmically incompressible, so R5 only
// attacks launch/tail overhead: persistent grid-stride kernel, 592 blocks
// x 512 threads, 2 tokens per warp-iteration.

struct V8 { float v[8]; };

__device__ __forceinline__ V8 ldg256_keep(const float* p) {
    V8 r;
    asm volatile(
        "ld.global.nc.L2::evict_last.v8.b32 {%0,%1,%2,%3,%4,%5,%6,%7}, [%8];"
        : "=f"(r.v[0]), "=f"(r.v[1]), "=f"(r.v[2]), "=f"(r.v[3]),
          "=f"(r.v[4]), "=f"(r.v[5]), "=f"(r.v[6]), "=f"(r.v[7])
        : "l"(p));
    return r;
}

__device__ __forceinline__ void stg_stream4(float* p, float a, float b, float c, float d) {
    asm volatile("st.global.cs.v4.f32 [%0], {%1,%2,%3,%4};"
                 :: "l"(p), "f"(a), "f"(b), "f"(c), "f"(d)
                 : "memory");
}

static constexpr int BLOCKS  = 592;   // 4 CTAs per SM (148 SMs)
static constexpr int THREADS = 512;   // 16 warps/CTA
static constexpr int TOTAL_WARPS = BLOCKS * (THREADS / 32);  // 9472

__global__ __launch_bounds__(THREADS) void twohot_kernel(
    const int* __restrict__ idx1,
    const int* __restrict__ idx2,
    const float* __restrict__ weight,   // [NUM_EMB, 256] f32
    float* __restrict__ out,            // [tokens, 256] f32
    int n_pairs)                        // n_tokens / 2
{
    const int warp_global = (blockIdx.x * blockDim.x + threadIdx.x) >> 5;
    const int lane = threadIdx.x & 31;
    const int off = lane * 8;

    for (int p = warp_global; p < n_pairs; p += TOTAL_WARPS) {
        const int t0 = p * 2;

        // Paired index loads (64-bit each, warp-broadcast).
        const int2 ia = *(const int2*)(idx1 + t0);
        const int2 ib = *(const int2*)(idx2 + t0);

        const float* p1a = weight + (size_t)ia.x * 256 + off;
        const float* p2a = weight + (size_t)ib.x * 256 + off;
        const float* p1b = weight + (size_t)ia.y * 256 + off;
        const float* p2b = weight + (size_t)ib.y * 256 + off;

        // 4 independent 256-bit gathers in flight.
        V8 e1a = ldg256_keep(p1a);
        V8 e2a = ldg256_keep(p2a);
        V8 e1b = ldg256_keep(p1b);
        V8 e2b = ldg256_keep(p2b);

        // i1==i2 has probability ~1e-5: handle with selects, no divergence.
        const bool same_a = (ia.x == ib.x);
        const bool same_b = (ia.y == ib.y);

        float ra[8], rb[8];
        #pragma unroll
        for (int i = 0; i < 8; i++) {
            ra[i] = same_a ? e1a.v[i] : e1a.v[i] + e2a.v[i];
            rb[i] = same_b ? e1b.v[i] : e1b.v[i] + e2b.v[i];
        }

        float* oa = out + (size_t)t0 * 256 + off;
        float* ob = oa + 256;
        stg_stream4(oa,     ra[0], ra[1], ra[2], ra[3]);
        stg_stream4(oa + 4, ra[4], ra[5], ra[6], ra[7]);
        stg_stream4(ob,     rb[0], rb[1], rb[2], rb[3]);
        stg_stream4(ob + 4, rb[4], rb[5], rb[6], rb[7]);
    }
}

extern "C" void kernel_launch(void* const* d_in, const int* in_sizes, int n_in,
                              void* d_out, int out_size)
{
    const int* idx1 = (const int*)d_in[0];        // input_one [B,S] int32
    const int* idx2 = (const int*)d_in[1];        // input_two [B,S] int32
    const float* weight = (const float*)d_in[2];  // weight [100000,256] f32

    float* out = (float*)d_out;

    const int n_tokens = in_sizes[0];             // 65536 (even)
    const int n_pairs = n_tokens / 2;
    (void)n_in; (void)out_size;

    twohot_kernel<<<BLOCKS, THREADS>>>(idx1, idx2, weight, out, n_pairs);
}

// round 6
// speedup vs baseline: 1.5475x; 1.5475x over previous
#include <cuda_runtime.h>
#include <stdint.h>

// TwoHotEmbedding: out[t,:] = w[i1[t],:]              if i1[t]==i2[t]
//                             w[i1[t],:] + w[i2[t],:]  otherwise
// B*S = 65536 tokens, D = 256 floats per row (1024 B = 32 lanes x 32 B).
//
// Model (R1-R5 evidence): kernel is pinned at ~24.3us by the chip-wide LTS
// (L2-crossing) cap: 201 MB of traffic (134 MB gather reads + 67 MB
// streaming writes) at ~8.3 TB/s (6300 B/cyc @LOCK scaled to NAT clock),
// invariant across kernel forms. One-shot warps are mandatory (R5's
// grid-stride loop serialized iterations and regressed to 41us).
// R6: identical one-shot 2-token/warp body, 512-thread blocks -> grid 2048
// to shave launch overhead (e2e-minus-kernel gap scales with grid size).

struct V8 { float v[8]; };

__device__ __forceinline__ V8 ldg256_keep(const float* p) {
    V8 r;
    asm volatile(
        "ld.global.nc.L2::evict_last.v8.b32 {%0,%1,%2,%3,%4,%5,%6,%7}, [%8];"
        : "=f"(r.v[0]), "=f"(r.v[1]), "=f"(r.v[2]), "=f"(r.v[3]),
          "=f"(r.v[4]), "=f"(r.v[5]), "=f"(r.v[6]), "=f"(r.v[7])
        : "l"(p));
    return r;
}

__device__ __forceinline__ void stg_stream4(float* p, float a, float b, float c, float d) {
    asm volatile("st.global.cs.v4.f32 [%0], {%1,%2,%3,%4};"
                 :: "l"(p), "f"(a), "f"(b), "f"(c), "f"(d)
                 : "memory");
}

static constexpr int THREADS = 512;   // 16 warps/CTA, 2 tokens/warp -> 32 tokens/CTA

__global__ __launch_bounds__(THREADS) void twohot_kernel(
    const int* __restrict__ idx1,
    const int* __restrict__ idx2,
    const float* __restrict__ weight,   // [NUM_EMB, 256] f32
    float* __restrict__ out,            // [tokens, 256] f32
    int n_tokens)
{
    const int warp_global = (blockIdx.x * blockDim.x + threadIdx.x) >> 5;
    const int lane = threadIdx.x & 31;
    const int t0 = warp_global * 2;            // first of 2 tokens
    if (t0 >= n_tokens) return;

    // Paired index loads (64-bit each, warp-broadcast).
    const int2 ia = *(const int2*)(idx1 + t0);
    const int2 ib = *(const int2*)(idx2 + t0);

    const int off = lane * 8;
    const float* p1a = weight + (size_t)ia.x * 256 + off;
    const float* p2a = weight + (size_t)ib.x * 256 + off;
    const float* p1b = weight + (size_t)ia.y * 256 + off;
    const float* p2b = weight + (size_t)ib.y * 256 + off;

    // 4 independent 256-bit gathers in flight.
    V8 e1a = ldg256_keep(p1a);
    V8 e2a = ldg256_keep(p2a);
    V8 e1b = ldg256_keep(p1b);
    V8 e2b = ldg256_keep(p2b);

    // i1==i2 has probability ~1e-5: handle with selects, no divergence.
    const bool same_a = (ia.x == ib.x);
    const bool same_b = (ia.y == ib.y);

    float ra[8], rb[8];
    #pragma unroll
    for (int i = 0; i < 8; i++) {
        ra[i] = same_a ? e1a.v[i] : e1a.v[i] + e2a.v[i];
        rb[i] = same_b ? e1b.v[i] : e1b.v[i] + e2b.v[i];
    }

    float* oa = out + (size_t)t0 * 256 + off;
    float* ob = oa + 256;
    stg_stream4(oa,     ra[0], ra[1], ra[2], ra[3]);
    stg_stream4(oa + 4, ra[4], ra[5], ra[6], ra[7]);
    stg_stream4(ob,     rb[0], rb[1], rb[2], rb[3]);
    stg_stream4(ob + 4, rb[4], rb[5], rb[6], rb[7]);
}

extern "C" void kernel_launch(void* const* d_in, const int* in_sizes, int n_in,
                              void* d_out, int out_size)
{
    const int* idx1 = (const int*)d_in[0];        // input_one [B,S] int32
    const int* idx2 = (const int*)d_in[1];        // input_two [B,S] int32
    const float* weight = (const float*)d_in[2];  // weight [100000,256] f32

    float* out = (float*)d_out;

    const int n_tokens = in_sizes[0];             // 65536
    (void)n_in; (void)out_size;

    // 16 warps/block, 2 tokens/warp -> 32 tokens per block -> 2048 blocks.
    const int tokens_per_block = (THREADS / 32) * 2;
    const int blocks = (n_tokens + tokens_per_block - 1) / tokens_per_block;
    twohot_kernel<<<blocks, THREADS>>>(idx1, idx2, weight, out, n_tokens);
}